// round 16
// baseline (speedup 1.0000x reference)
#include <cuda_runtime.h>
#include <cuda_bf16.h>
#include <cuda_fp16.h>
#include <math.h>
#include <stdint.h>

#define NN    100000
#define NNP   100096           // padded rows for MMA tiles (multiple of 128)
#define EE    3200000
#define ET    (EE + NN)
#define HIDC  256
#define NHEAD 8
#define OUTC  40

// ---------------- scratch (static __device__, no allocations) ----------------
__device__ __align__(128) __half g_lin16[(size_t)NN * HIDC];        // h in fp16 (edge gather)
__device__ __align__(128) __half g_jk   [(size_t)NN * HIDC];        // running JK max (fp16)
__device__ __align__(128) float g_esrc [NN * NHEAD];
__device__ __align__(128) float g_edst [NN * NHEAD];
__device__ __align__(128) __nv_bfloat16 g_abf[(size_t)NNP * 512];   // bf16 activations (K-major)
__device__ __align__(128) __nv_bfloat16 g_bbf[3 * 256 * 512];       // bf16 weights (transposed)
__device__ __align__(128) int   g_cnt   [NN];
__device__ __align__(128) int   g_tmp   [NN];
__device__ __align__(128) int   g_bsum  [256];
__device__ __align__(128) int   g_rowptr[NN + 1];
__device__ __align__(128) int   g_cursor[NN];
__device__ __align__(128) int   g_csrsrc[ET];
__device__ int g_ticket[3];
__device__ int g_odd_nonzero;

// ---------------- portable PTX helpers (sm_80-class ops only) ----------------
__device__ __forceinline__ uint32_t s2u(const void* p) {
    return (uint32_t)__cvta_generic_to_shared(p);
}
__device__ __forceinline__ void cpa16(uint32_t dst, const void* src) {
    asm volatile("cp.async.cg.shared.global [%0], [%1], 16;" :: "r"(dst), "l"(src));
}
#define CP_COMMIT() asm volatile("cp.async.commit_group;" ::: "memory")
#define CP_WAIT0()  asm volatile("cp.async.wait_group 0;" ::: "memory")

__device__ __forceinline__ void ldm4(uint32_t* r, uint32_t addr) {
    asm volatile("ldmatrix.sync.aligned.m8n8.x4.shared.b16 {%0,%1,%2,%3}, [%4];"
        : "=r"(r[0]), "=r"(r[1]), "=r"(r[2]), "=r"(r[3]) : "r"(addr));
}
__device__ __forceinline__ void mma16816(float* d, const uint32_t* a, uint32_t b0, uint32_t b1) {
    asm volatile("mma.sync.aligned.m16n8k16.row.col.f32.bf16.bf16.f32 "
        "{%0,%1,%2,%3}, {%4,%5,%6,%7}, {%8,%9}, {%0,%1,%2,%3};"
        : "+f"(d[0]), "+f"(d[1]), "+f"(d[2]), "+f"(d[3])
        : "r"(a[0]), "r"(a[1]), "r"(a[2]), "r"(a[3]), "r"(b0), "r"(b1));
}

// ---------------- CSR build ----------------
__global__ void k_zero() {
    int i = blockIdx.x * blockDim.x + threadIdx.x;
    if (i < NN) g_cnt[i] = 0;
    if (i < 3) g_ticket[i] = 0;
    if (i == 3) g_odd_nonzero = 0;
}
__global__ void k_detect(const int* __restrict__ ei32) {
    int i = blockIdx.x * blockDim.x + threadIdx.x;
    if (i < 4096 && ei32[2 * i + 1] != 0) atomicOr(&g_odd_nonzero, 1);
}
__global__ void k_hist(const void* __restrict__ ei) {
    int e = blockIdx.x * blockDim.x + threadIdx.x;
    if (e >= ET) return;
    int dst;
    if (e >= EE) dst = e - EE;
    else if (g_odd_nonzero == 0) dst = (int)((const long long*)ei)[(size_t)EE + e];
    else dst = ((const int*)ei)[(size_t)EE + e];
    atomicAdd(&g_cnt[dst], 1);
}
#define SCB 512
#define NSCB ((NN + SCB - 1) / SCB)
__global__ void k_scan1() {
    __shared__ int sh[SCB];
    const int t = threadIdx.x, i = blockIdx.x * SCB + t;
    int v = (i < NN) ? g_cnt[i] : 0;
    sh[t] = v; __syncthreads();
    for (int off = 1; off < SCB; off <<= 1) {
        int u = (t >= off) ? sh[t - off] : 0;
        __syncthreads(); sh[t] += u; __syncthreads();
    }
    if (i < NN) g_tmp[i] = sh[t];
    if (t == SCB - 1) g_bsum[blockIdx.x] = sh[t];
}
__global__ void k_scan2() {
    __shared__ int sh[256];
    const int t = threadIdx.x;
    int v = (t < NSCB) ? g_bsum[t] : 0;
    sh[t] = v; __syncthreads();
    for (int off = 1; off < 256; off <<= 1) {
        int u = (t >= off) ? sh[t - off] : 0;
        __syncthreads(); sh[t] += u; __syncthreads();
    }
    g_bsum[t] = sh[t] - v;
}
__global__ void k_scan3() {
    int i = blockIdx.x * blockDim.x + threadIdx.x;
    if (i < NN) {
        int r = g_tmp[i] - g_cnt[i] + g_bsum[i >> 9];
        g_rowptr[i] = r; g_cursor[i] = r;
    }
    if (i == 0) g_rowptr[NN] = ET;
}
__global__ void k_scatter(const void* __restrict__ ei) {
    int e = blockIdx.x * blockDim.x + threadIdx.x;
    if (e >= ET) return;
    int src, dst;
    if (e >= EE) { src = e - EE; dst = src; }
    else if (g_odd_nonzero == 0) {
        const long long* p = (const long long*)ei;
        src = (int)p[e]; dst = (int)p[(size_t)EE + e];
    } else {
        const int* p = (const int*)ei;
        src = p[e]; dst = p[(size_t)EE + e];
    }
    g_csrsrc[atomicAdd(&g_cursor[dst], 1)] = src;
}

// ---------------- bf16 packers (plain bf16, 1-segment) ----------------
// x [NN,500] fp32 -> g_abf [NNP,512] bf16, pad->0
__global__ void k_cvtX(const float* __restrict__ x) {
    int idx = blockIdx.x * blockDim.x + threadIdx.x;       // n*128 + g
    if (idx >= NNP * 128) return;
    int n = idx >> 7, c = (idx & 127) * 4;
    float4 v = make_float4(0.f, 0.f, 0.f, 0.f);
    if (n < NN && c < 500) v = *(const float4*)(x + (size_t)n * 500 + c);
    __nv_bfloat16 hi[4];
    const float* vf = (const float*)&v;
#pragma unroll
    for (int j = 0; j < 4; j++) hi[j] = __float2bfloat16(vf[j]);
    *(uint2*)&g_abf[(size_t)n * 512 + c] = *(uint2*)hi;
}
// W [K,256] fp32 -> out [256][Kpad] bf16 (transposed)
__global__ void k_cvtW(const float* __restrict__ W, __nv_bfloat16* __restrict__ out,
                       int K, int Kpad) {
    int idx = blockIdx.x * blockDim.x + threadIdx.x;
    if (idx >= Kpad * 256) return;
    int k = idx >> 8, n = idx & 255;
    float v = (k < K) ? W[(size_t)k * 256 + n] : 0.f;
    out[(size_t)n * Kpad + k] = __float2bfloat16(v);
}

// ---------------- HMMA GEMM (plain bf16) + fused logits, fp16 C --------------
// 128x128 tile, 8 warps (2x4), warp tile 64x32 (one head), dbuf cp.async k32.
#define SROW 80
__global__ __launch_bounds__(256) void k_mma(
    const __nv_bfloat16* __restrict__ Ap, const __nv_bfloat16* __restrict__ Bp,
    const float* __restrict__ asrc, const float* __restrict__ adst,
    __half* __restrict__ C16, int Kpad)
{
    __shared__ __align__(128) char shA[2][128 * SROW];
    __shared__ __align__(128) char shB[2][128 * SROW];
    __shared__ float sas[128], sad[128];

    const int tid = threadIdx.x, wid = tid >> 5, lane = tid & 31;
    const int warp_m = wid >> 2, warp_n = wid & 3;
    const int bm = blockIdx.y * 128, bn = blockIdx.x * 128;
    const int ntiles = Kpad >> 5;

    if (tid < 128) sas[tid] = asrc[bn + tid];
    else sad[tid - 128] = adst[bn + tid - 128];

    const uint32_t sA0 = s2u(shA[0]), sB0 = s2u(shB[0]);
    const uint32_t bufStride = 128 * SROW;

    float acc[4][4][4];
#pragma unroll
    for (int i = 0; i < 4; i++)
#pragma unroll
        for (int j = 0; j < 4; j++)
#pragma unroll
            for (int q = 0; q < 4; q++) acc[i][j][q] = 0.f;

    // prefetch tile 0
    {
#pragma unroll
        for (int p = 0; p < 2; p++) {
            int q = tid + p * 256, row = q >> 2, ch = q & 3;
            cpa16(sA0 + row * SROW + ch * 16, Ap + (size_t)(bm + row) * Kpad + ch * 8);
            cpa16(sB0 + row * SROW + ch * 16, Bp + (size_t)(bn + row) * Kpad + ch * 8);
        }
        CP_COMMIT();
    }

    const uint32_t a_off = (warp_m * 64 + (lane & 15)) * SROW + (lane >> 4) * 16;
    const uint32_t b_off = (warp_n * 32 + (lane & 15)) * SROW + (lane >> 4) * 16;

    for (int t = 0; t < ntiles; t++) {
        CP_WAIT0();
        __syncthreads();
        if (t + 1 < ntiles) {
            const int kt = t + 1, buf = kt & 1, col = kt * 32;
#pragma unroll
            for (int p = 0; p < 2; p++) {
                int q = tid + p * 256, row = q >> 2, ch = q & 3;
                cpa16(sA0 + buf * bufStride + row * SROW + ch * 16,
                      Ap + (size_t)(bm + row) * Kpad + col + ch * 8);
                cpa16(sB0 + buf * bufStride + row * SROW + ch * 16,
                      Bp + (size_t)(bn + row) * Kpad + col + ch * 8);
            }
            CP_COMMIT();
        }
        const uint32_t aBase = sA0 + (t & 1) * bufStride + a_off;
        const uint32_t bBase = sB0 + (t & 1) * bufStride + b_off;
#pragma unroll
        for (int ks = 0; ks < 2; ks++) {
            uint32_t af[4][4], bf2[2][4];
#pragma unroll
            for (int mt = 0; mt < 4; mt++)
                ldm4(af[mt], aBase + mt * 16 * SROW + ks * 32);
#pragma unroll
            for (int np = 0; np < 2; np++)
                ldm4(bf2[np], bBase + np * 16 * SROW + ks * 32);
#pragma unroll
            for (int mt = 0; mt < 4; mt++)
#pragma unroll
                for (int nt = 0; nt < 4; nt++) {
                    const int np = nt >> 1, od = nt & 1;
                    mma16816(acc[mt][nt], af[mt], bf2[np][od], bf2[np][2 + od]);
                }
        }
        __syncthreads();
    }

    // epilogue: fp16 C store + fused per-head attention logits (warp owns one head)
    const int qr = lane >> 2, qc = lane & 3;
    const int head = (bn >> 5) + warp_n;
#pragma unroll
    for (int mt = 0; mt < 4; mt++) {
        float es0 = 0.f, es1 = 0.f, ed0 = 0.f, ed1 = 0.f;
#pragma unroll
        for (int nt = 0; nt < 4; nt++) {
            const int c = warp_n * 32 + nt * 8 + qc * 2;
            es0 = fmaf(acc[mt][nt][0], sas[c], fmaf(acc[mt][nt][1], sas[c + 1], es0));
            es1 = fmaf(acc[mt][nt][2], sas[c], fmaf(acc[mt][nt][3], sas[c + 1], es1));
            ed0 = fmaf(acc[mt][nt][0], sad[c], fmaf(acc[mt][nt][1], sad[c + 1], ed0));
            ed1 = fmaf(acc[mt][nt][2], sad[c], fmaf(acc[mt][nt][3], sad[c + 1], ed1));
        }
        es0 += __shfl_xor_sync(0xffffffffu, es0, 1); es0 += __shfl_xor_sync(0xffffffffu, es0, 2);
        es1 += __shfl_xor_sync(0xffffffffu, es1, 1); es1 += __shfl_xor_sync(0xffffffffu, es1, 2);
        ed0 += __shfl_xor_sync(0xffffffffu, ed0, 1); ed0 += __shfl_xor_sync(0xffffffffu, ed0, 2);
        ed1 += __shfl_xor_sync(0xffffffffu, ed1, 1); ed1 += __shfl_xor_sync(0xffffffffu, ed1, 2);
        const int r0 = bm + warp_m * 64 + mt * 16 + qr;
        const int r1 = r0 + 8;
        if (qc == 0) {
            if (r0 < NN) { g_esrc[r0 * 8 + head] = es0; g_edst[r0 * 8 + head] = ed0; }
            if (r1 < NN) { g_esrc[r1 * 8 + head] = es1; g_edst[r1 * 8 + head] = ed1; }
        }
#pragma unroll
        for (int nt = 0; nt < 4; nt++) {
            const int c = bn + warp_n * 32 + nt * 8 + qc * 2;
            if (r0 < NN) *(__half2*)(C16 + (size_t)r0 * HIDC + c) =
                __floats2half2_rn(acc[mt][nt][0], acc[mt][nt][1]);
            if (r1 < NN) *(__half2*)(C16 + (size_t)r1 * HIDC + c) =
                __floats2half2_rn(acc[mt][nt][2], acc[mt][nt][3]);
        }
    }
}

// ---------------- single-pass segment softmax + aggregation ------------------
// Persistent warps + global ticket counter: each warp pulls node ids dynamically
// (removes Poisson-degree straggler loss + wave quantization). Deterministic:
// each node processed by exactly one warp, in CSR order.
#define EDGE_BLOCKS (148 * 6)
__global__ __launch_bounds__(256) void k_edge(const float* __restrict__ bias,
                       int do_elu, int do_cvt, int jk_max, int layer) {
    const int lane = threadIdx.x & 31;
    const int head = lane & 7;
    const int sub  = lane >> 3;
    const int c0 = head * 32 + sub * 8;

    for (;;) {
        int n;
        if (lane == 0) n = atomicAdd(&g_ticket[layer], 1);
        n = __shfl_sync(0xffffffffu, n, 0);
        if (n >= NN) return;

        const int beg = g_rowptr[n], end = g_rowptr[n + 1];
        const float edh = g_edst[n * 8 + head];

        float acc[8];
#pragma unroll
        for (int j = 0; j < 8; j++) acc[j] = 0.f;
        float sw = 0.f;

        int i = beg;
        for (; i + 2 <= end; i += 2) {
            const int s0 = g_csrsrc[i], s1 = g_csrsrc[i + 1];
            float t0 = g_esrc[s0 * 8 + head] + edh;
            float t1 = g_esrc[s1 * 8 + head] + edh;
            uint4 raw0 = *(const uint4*)(g_lin16 + (size_t)s0 * HIDC + c0);
            uint4 raw1 = *(const uint4*)(g_lin16 + (size_t)s1 * HIDC + c0);
            t0 = (t0 > 0.f) ? t0 : 0.2f * t0;
            t1 = (t1 > 0.f) ? t1 : 0.2f * t1;
            const float w0 = __expf(t0), w1 = __expf(t1);
            sw += w0 + w1;
            const __half2* h0 = (const __half2*)&raw0;
            const __half2* h1 = (const __half2*)&raw1;
#pragma unroll
            for (int q = 0; q < 4; q++) {
                float2 f0 = __half22float2(h0[q]);
                float2 f1 = __half22float2(h1[q]);
                acc[2*q]   = fmaf(w0, f0.x, fmaf(w1, f1.x, acc[2*q]));
                acc[2*q+1] = fmaf(w0, f0.y, fmaf(w1, f1.y, acc[2*q+1]));
            }
        }
        if (i < end) {
            const int s = g_csrsrc[i];
            float t = g_esrc[s * 8 + head] + edh;
            t = (t > 0.f) ? t : 0.2f * t;
            const float w = __expf(t);
            sw += w;
            uint4 raw = *(const uint4*)(g_lin16 + (size_t)s * HIDC + c0);
            const __half2* h2 = (const __half2*)&raw;
#pragma unroll
            for (int q = 0; q < 4; q++) {
                float2 f = __half22float2(h2[q]);
                acc[2*q]   = fmaf(w, f.x, acc[2*q]);
                acc[2*q+1] = fmaf(w, f.y, acc[2*q+1]);
            }
        }

        const float inv = 1.f / (sw + 1e-16f);
        float o[8];
#pragma unroll
        for (int j = 0; j < 8; j++) {
            float vv = acc[j] * inv + bias[c0 + j];
            if (do_elu) vv = (vv > 0.f) ? vv : (__expf(vv) - 1.f);
            o[j] = vv;
        }
        // running JK max in fp16
        __align__(16) __half hv[8];
#pragma unroll
        for (int j = 0; j < 8; j++) hv[j] = __float2half(o[j]);
        if (jk_max) {
            uint4 old = *(const uint4*)&g_jk[(size_t)n * HIDC + c0];
            const __half* ov = (const __half*)&old;
#pragma unroll
            for (int j = 0; j < 8; j++) hv[j] = __hmax(hv[j], ov[j]);
        }
        *(uint4*)&g_jk[(size_t)n * HIDC + c0] = *(uint4*)hv;

        if (do_cvt) {
            __align__(16) __nv_bfloat16 hb[8];
#pragma unroll
            for (int j = 0; j < 8; j++) hb[j] = __float2bfloat16(o[j]);
            *(uint4*)&g_abf[(size_t)n * 256 + c0] = *(uint4*)hb;
        }
    }
}

// ---------------- fused final linear (on fp16 JK buffer) + log_softmax ------
__global__ __launch_bounds__(160) void k_final(
    const float* __restrict__ Wf, const float* __restrict__ bf, float* __restrict__ out)
{
    __shared__ __align__(16) float sW[HIDC * OUTC];
    __shared__ float sb[OUTC];
    __shared__ __align__(16) float sl[32][OUTC];
    const int t = threadIdx.x;
    for (int i = t; i < HIDC * OUTC; i += 160) sW[i] = Wf[i];
    if (t < OUTC) sb[t] = bf[t];
    __syncthreads();

    const int r = t / 5;
    const int og = (t % 5) * 8;
    const int node = blockIdx.x * 32 + r;
    float acc[8];
#pragma unroll
    for (int j = 0; j < 8; j++) acc[j] = 0.f;
    const __half* pj = g_jk + (size_t)node * HIDC;
    for (int k = 0; k < HIDC; k += 2) {
        float2 vv = __half22float2(*(const __half2*)&pj[k]);
#pragma unroll
        for (int s = 0; s < 2; s++) {
            const float v = (s == 0) ? vv.x : vv.y;
            const float4* wp = (const float4*)&sW[(k + s) * OUTC + og];
            float4 w0 = wp[0], w1 = wp[1];
            acc[0] = fmaf(v, w0.x, acc[0]); acc[1] = fmaf(v, w0.y, acc[1]);
            acc[2] = fmaf(v, w0.z, acc[2]); acc[3] = fmaf(v, w0.w, acc[3]);
            acc[4] = fmaf(v, w1.x, acc[4]); acc[5] = fmaf(v, w1.y, acc[5]);
            acc[6] = fmaf(v, w1.z, acc[6]); acc[7] = fmaf(v, w1.w, acc[7]);
        }
    }
#pragma unroll
    for (int j = 0; j < 8; j++) acc[j] += sb[og + j];
    *(float4*)&sl[r][og]     = make_float4(acc[0], acc[1], acc[2], acc[3]);
    *(float4*)&sl[r][og + 4] = make_float4(acc[4], acc[5], acc[6], acc[7]);
    __syncthreads();

    if (t < 32) {
        const int nd = blockIdx.x * 32 + t;
        float m = -1e30f;
        for (int o = 0; o < OUTC; o++) m = fmaxf(m, sl[t][o]);
        float ssum = 0.f;
        for (int o = 0; o < OUTC; o++) ssum += expf(sl[t][o] - m);
        const float lse = m + logf(ssum);
        for (int o = 0; o < OUTC; o++) out[(size_t)nd * OUTC + o] = sl[t][o] - lse;
    }
}

// ---------------- launch ----------------
extern "C" void kernel_launch(void* const* d_in, const int* in_sizes, int n_in,
                              void* d_out, int out_size)
{
    (void)in_sizes; (void)n_in; (void)out_size;
    const float* x  = (const float*)d_in[0];
    const void*  ei = d_in[1];
    const float* W[3]  = {(const float*)d_in[2], (const float*)d_in[6],  (const float*)d_in[10]};
    const float* As[3] = {(const float*)d_in[3], (const float*)d_in[7],  (const float*)d_in[11]};
    const float* Ad[3] = {(const float*)d_in[4], (const float*)d_in[8],  (const float*)d_in[12]};
    const float* Bb[3] = {(const float*)d_in[5], (const float*)d_in[9],  (const float*)d_in[13]};
    const float* Wf = (const float*)d_in[14];
    const float* bf = (const float*)d_in[15];
    float* out = (float*)d_out;

    __half* lin16;
    __nv_bfloat16 *abf, *bbf;
    cudaGetSymbolAddress((void**)&lin16, g_lin16);
    cudaGetSymbolAddress((void**)&abf, g_abf);
    cudaGetSymbolAddress((void**)&bbf, g_bbf);

    // one-time host resources (no device memory): side stream + fork/join events
    static cudaStream_t s_csr = 0;
    static cudaEvent_t ev_fork = 0, ev_csr = 0;
    if (!s_csr) {
        cudaStreamCreateWithFlags(&s_csr, cudaStreamNonBlocking);
        cudaEventCreateWithFlags(&ev_fork, cudaEventDisableTiming);
        cudaEventCreateWithFlags(&ev_csr, cudaEventDisableTiming);
    }

    const int Ks[3]    = {500, 256, 256};
    const int Kpads[3] = {512, 256, 256};
    dim3 mgrid(2, NNP / 128);

    // ---- fork: CSR build on side stream (independent of dense chain) ----
    cudaEventRecord(ev_fork, 0);
    cudaStreamWaitEvent(s_csr, ev_fork, 0);
    k_zero<<<(NN + 255) / 256, 256, 0, s_csr>>>();
    k_detect<<<16, 256, 0, s_csr>>>((const int*)ei);
    k_hist<<<(ET + 255) / 256, 256, 0, s_csr>>>(ei);
    k_scan1<<<NSCB, SCB, 0, s_csr>>>();
    k_scan2<<<1, 256, 0, s_csr>>>();
    k_scan3<<<(NN + 255) / 256, 256, 0, s_csr>>>();
    k_scatter<<<(ET + 255) / 256, 256, 0, s_csr>>>(ei);
    cudaEventRecord(ev_csr, s_csr);

    // ---- dense chain on default stream ----
    k_cvtX<<<(NNP * 128 + 255) / 256, 256>>>(x);
    for (int l = 0; l < 3; l++)
        k_cvtW<<<(Kpads[l] * 256 + 255) / 256, 256>>>(W[l], bbf + (size_t)l * 256 * 512,
                                                       Ks[l], Kpads[l]);
    k_mma<<<mgrid, 256>>>(abf, bbf, As[0], Ad[0], lin16, Kpads[0]);

    // ---- join: edge needs the CSR ----
    cudaStreamWaitEvent(0, ev_csr, 0);
    k_edge<<<EDGE_BLOCKS, 256>>>(Bb[0], 1, 1, 0, 0);

    for (int l = 1; l < 3; l++) {
        k_mma<<<mgrid, 256>>>(abf, bbf + (size_t)l * 256 * 512,
                              As[l], Ad[l], lin16, Kpads[l]);
        k_edge<<<EDGE_BLOCKS, 256>>>(Bb[l],
                                     (l < 2) ? 1 : 0, (l < 2) ? 1 : 0, 1, l);
    }
    k_final<<<NN / 32, 160>>>(Wf, bf, out);
}

// round 17
// speedup vs baseline: 1.0103x; 1.0103x over previous
#include <cuda_runtime.h>
#include <cuda_bf16.h>
#include <cuda_fp16.h>
#include <math.h>
#include <stdint.h>

#define NN    100000
#define NNP   100096           // padded rows for MMA tiles (multiple of 128)
#define EE    3200000
#define ET    (EE + NN)
#define HIDC  256
#define NHEAD 8
#define OUTC  40

// ---------------- scratch (static __device__, no allocations) ----------------
__device__ __align__(128) __half g_lin16[(size_t)NN * HIDC];        // h in fp16 (edge gather)
__device__ __align__(128) __half g_jk   [(size_t)NN * HIDC];        // running JK max (fp16)
__device__ __align__(128) float g_esrc [NN * NHEAD];
__device__ __align__(128) float g_edst [NN * NHEAD];
__device__ __align__(128) __nv_bfloat16 g_abf[(size_t)NNP * 512];   // bf16 activations (K-major)
__device__ __align__(128) __nv_bfloat16 g_bbf[3 * 256 * 512];       // bf16 weights (transposed)
__device__ __align__(128) int   g_cnt   [NN];
__device__ __align__(128) int   g_tmp   [NN];
__device__ __align__(128) int   g_bsum  [256];
__device__ __align__(128) int   g_rowptr[NN + 1];
__device__ __align__(128) int   g_cursor[NN];
__device__ __align__(128) int   g_csrsrc[ET];
__device__ int g_odd_nonzero;

// ---------------- portable PTX helpers (sm_80-class ops only) ----------------
__device__ __forceinline__ uint32_t s2u(const void* p) {
    return (uint32_t)__cvta_generic_to_shared(p);
}
__device__ __forceinline__ void cpa16(uint32_t dst, const void* src) {
    asm volatile("cp.async.cg.shared.global [%0], [%1], 16;" :: "r"(dst), "l"(src));
}
#define CP_COMMIT() asm volatile("cp.async.commit_group;" ::: "memory")
#define CP_WAIT0()  asm volatile("cp.async.wait_group 0;" ::: "memory")

__device__ __forceinline__ void ldm4(uint32_t* r, uint32_t addr) {
    asm volatile("ldmatrix.sync.aligned.m8n8.x4.shared.b16 {%0,%1,%2,%3}, [%4];"
        : "=r"(r[0]), "=r"(r[1]), "=r"(r[2]), "=r"(r[3]) : "r"(addr));
}
__device__ __forceinline__ void mma16816(float* d, const uint32_t* a, uint32_t b0, uint32_t b1) {
    asm volatile("mma.sync.aligned.m16n8k16.row.col.f32.bf16.bf16.f32 "
        "{%0,%1,%2,%3}, {%4,%5,%6,%7}, {%8,%9}, {%0,%1,%2,%3};"
        : "+f"(d[0]), "+f"(d[1]), "+f"(d[2]), "+f"(d[3])
        : "r"(a[0]), "r"(a[1]), "r"(a[2]), "r"(a[3]), "r"(b0), "r"(b1));
}

// ---------------- CSR build ----------------
__global__ void k_zero() {
    int i = blockIdx.x * blockDim.x + threadIdx.x;
    if (i < NN) g_cnt[i] = 0;
    if (i == 0) g_odd_nonzero = 0;
}
__global__ void k_detect(const int* __restrict__ ei32) {
    int i = blockIdx.x * blockDim.x + threadIdx.x;
    if (i < 4096 && ei32[2 * i + 1] != 0) atomicOr(&g_odd_nonzero, 1);
}
__global__ void k_hist(const void* __restrict__ ei) {
    int e = blockIdx.x * blockDim.x + threadIdx.x;
    if (e >= ET) return;
    int dst;
    if (e >= EE) dst = e - EE;
    else if (g_odd_nonzero == 0) dst = (int)((const long long*)ei)[(size_t)EE + e];
    else dst = ((const int*)ei)[(size_t)EE + e];
    atomicAdd(&g_cnt[dst], 1);
}
#define SCB 512
#define NSCB ((NN + SCB - 1) / SCB)
__global__ void k_scan1() {
    __shared__ int sh[SCB];
    const int t = threadIdx.x, i = blockIdx.x * SCB + t;
    int v = (i < NN) ? g_cnt[i] : 0;
    sh[t] = v; __syncthreads();
    for (int off = 1; off < SCB; off <<= 1) {
        int u = (t >= off) ? sh[t - off] : 0;
        __syncthreads(); sh[t] += u; __syncthreads();
    }
    if (i < NN) g_tmp[i] = sh[t];
    if (t == SCB - 1) g_bsum[blockIdx.x] = sh[t];
}
__global__ void k_scan2() {
    __shared__ int sh[256];
    const int t = threadIdx.x;
    int v = (t < NSCB) ? g_bsum[t] : 0;
    sh[t] = v; __syncthreads();
    for (int off = 1; off < 256; off <<= 1) {
        int u = (t >= off) ? sh[t - off] : 0;
        __syncthreads(); sh[t] += u; __syncthreads();
    }
    g_bsum[t] = sh[t] - v;
}
__global__ void k_scan3() {
    int i = blockIdx.x * blockDim.x + threadIdx.x;
    if (i < NN) {
        int r = g_tmp[i] - g_cnt[i] + g_bsum[i >> 9];
        g_rowptr[i] = r; g_cursor[i] = r;
    }
    if (i == 0) g_rowptr[NN] = ET;
}
__global__ void k_scatter(const void* __restrict__ ei) {
    int e = blockIdx.x * blockDim.x + threadIdx.x;
    if (e >= ET) return;
    int src, dst;
    if (e >= EE) { src = e - EE; dst = src; }
    else if (g_odd_nonzero == 0) {
        const long long* p = (const long long*)ei;
        src = (int)p[e]; dst = (int)p[(size_t)EE + e];
    } else {
        const int* p = (const int*)ei;
        src = p[e]; dst = p[(size_t)EE + e];
    }
    g_csrsrc[atomicAdd(&g_cursor[dst], 1)] = src;
}

// ---------------- bf16 packers (plain bf16, 1-segment) ----------------
// x [NN,500] fp32 -> g_abf [NNP,512] bf16, pad->0
__global__ void k_cvtX(const float* __restrict__ x) {
    int idx = blockIdx.x * blockDim.x + threadIdx.x;       // n*128 + g
    if (idx >= NNP * 128) return;
    int n = idx >> 7, c = (idx & 127) * 4;
    float4 v = make_float4(0.f, 0.f, 0.f, 0.f);
    if (n < NN && c < 500) v = __ldcs((const float4*)(x + (size_t)n * 500 + c));
    __nv_bfloat16 hi[4];
    const float* vf = (const float*)&v;
#pragma unroll
    for (int j = 0; j < 4; j++) hi[j] = __float2bfloat16(vf[j]);
    *(uint2*)&g_abf[(size_t)n * 512 + c] = *(uint2*)hi;
}
// W [K,256] fp32 -> out [256][Kpad] bf16 (transposed)
__global__ void k_cvtW(const float* __restrict__ W, __nv_bfloat16* __restrict__ out,
                       int K, int Kpad) {
    int idx = blockIdx.x * blockDim.x + threadIdx.x;
    if (idx >= Kpad * 256) return;
    int k = idx >> 8, n = idx & 255;
    float v = (k < K) ? W[(size_t)k * 256 + n] : 0.f;
    out[(size_t)n * Kpad + k] = __float2bfloat16(v);
}

// ---------------- HMMA GEMM (plain bf16) + fused logits, fp16 C --------------
// 128x128 tile, 8 warps (2x4), warp tile 64x32 (one head), dbuf cp.async k32.
#define SROW 80
__global__ __launch_bounds__(256) void k_mma(
    const __nv_bfloat16* __restrict__ Ap, const __nv_bfloat16* __restrict__ Bp,
    const float* __restrict__ asrc, const float* __restrict__ adst,
    __half* __restrict__ C16, int Kpad)
{
    __shared__ __align__(128) char shA[2][128 * SROW];
    __shared__ __align__(128) char shB[2][128 * SROW];
    __shared__ float sas[128], sad[128];

    const int tid = threadIdx.x, wid = tid >> 5, lane = tid & 31;
    const int warp_m = wid >> 2, warp_n = wid & 3;
    const int bm = blockIdx.y * 128, bn = blockIdx.x * 128;
    const int ntiles = Kpad >> 5;

    if (tid < 128) sas[tid] = asrc[bn + tid];
    else sad[tid - 128] = adst[bn + tid - 128];

    const uint32_t sA0 = s2u(shA[0]), sB0 = s2u(shB[0]);
    const uint32_t bufStride = 128 * SROW;

    float acc[4][4][4];
#pragma unroll
    for (int i = 0; i < 4; i++)
#pragma unroll
        for (int j = 0; j < 4; j++)
#pragma unroll
            for (int q = 0; q < 4; q++) acc[i][j][q] = 0.f;

    // prefetch tile 0
    {
#pragma unroll
        for (int p = 0; p < 2; p++) {
            int q = tid + p * 256, row = q >> 2, ch = q & 3;
            cpa16(sA0 + row * SROW + ch * 16, Ap + (size_t)(bm + row) * Kpad + ch * 8);
            cpa16(sB0 + row * SROW + ch * 16, Bp + (size_t)(bn + row) * Kpad + ch * 8);
        }
        CP_COMMIT();
    }

    const uint32_t a_off = (warp_m * 64 + (lane & 15)) * SROW + (lane >> 4) * 16;
    const uint32_t b_off = (warp_n * 32 + (lane & 15)) * SROW + (lane >> 4) * 16;

    for (int t = 0; t < ntiles; t++) {
        CP_WAIT0();
        __syncthreads();
        if (t + 1 < ntiles) {
            const int kt = t + 1, buf = kt & 1, col = kt * 32;
#pragma unroll
            for (int p = 0; p < 2; p++) {
                int q = tid + p * 256, row = q >> 2, ch = q & 3;
                cpa16(sA0 + buf * bufStride + row * SROW + ch * 16,
                      Ap + (size_t)(bm + row) * Kpad + col + ch * 8);
                cpa16(sB0 + buf * bufStride + row * SROW + ch * 16,
                      Bp + (size_t)(bn + row) * Kpad + col + ch * 8);
            }
            CP_COMMIT();
        }
        const uint32_t aBase = sA0 + (t & 1) * bufStride + a_off;
        const uint32_t bBase = sB0 + (t & 1) * bufStride + b_off;
#pragma unroll
        for (int ks = 0; ks < 2; ks++) {
            uint32_t af[4][4], bf2[2][4];
#pragma unroll
            for (int mt = 0; mt < 4; mt++)
                ldm4(af[mt], aBase + mt * 16 * SROW + ks * 32);
#pragma unroll
            for (int np = 0; np < 2; np++)
                ldm4(bf2[np], bBase + np * 16 * SROW + ks * 32);
#pragma unroll
            for (int mt = 0; mt < 4; mt++)
#pragma unroll
                for (int nt = 0; nt < 4; nt++) {
                    const int np = nt >> 1, od = nt & 1;
                    mma16816(acc[mt][nt], af[mt], bf2[np][od], bf2[np][2 + od]);
                }
        }
        __syncthreads();
    }

    // epilogue: fp16 C store + fused per-head attention logits (warp owns one head)
    const int qr = lane >> 2, qc = lane & 3;
    const int head = (bn >> 5) + warp_n;
#pragma unroll
    for (int mt = 0; mt < 4; mt++) {
        float es0 = 0.f, es1 = 0.f, ed0 = 0.f, ed1 = 0.f;
#pragma unroll
        for (int nt = 0; nt < 4; nt++) {
            const int c = warp_n * 32 + nt * 8 + qc * 2;
            es0 = fmaf(acc[mt][nt][0], sas[c], fmaf(acc[mt][nt][1], sas[c + 1], es0));
            es1 = fmaf(acc[mt][nt][2], sas[c], fmaf(acc[mt][nt][3], sas[c + 1], es1));
            ed0 = fmaf(acc[mt][nt][0], sad[c], fmaf(acc[mt][nt][1], sad[c + 1], ed0));
            ed1 = fmaf(acc[mt][nt][2], sad[c], fmaf(acc[mt][nt][3], sad[c + 1], ed1));
        }
        es0 += __shfl_xor_sync(0xffffffffu, es0, 1); es0 += __shfl_xor_sync(0xffffffffu, es0, 2);
        es1 += __shfl_xor_sync(0xffffffffu, es1, 1); es1 += __shfl_xor_sync(0xffffffffu, es1, 2);
        ed0 += __shfl_xor_sync(0xffffffffu, ed0, 1); ed0 += __shfl_xor_sync(0xffffffffu, ed0, 2);
        ed1 += __shfl_xor_sync(0xffffffffu, ed1, 1); ed1 += __shfl_xor_sync(0xffffffffu, ed1, 2);
        const int r0 = bm + warp_m * 64 + mt * 16 + qr;
        const int r1 = r0 + 8;
        if (qc == 0) {
            if (r0 < NN) { g_esrc[r0 * 8 + head] = es0; g_edst[r0 * 8 + head] = ed0; }
            if (r1 < NN) { g_esrc[r1 * 8 + head] = es1; g_edst[r1 * 8 + head] = ed1; }
        }
#pragma unroll
        for (int nt = 0; nt < 4; nt++) {
            const int c = bn + warp_n * 32 + nt * 8 + qc * 2;
            if (r0 < NN) *(__half2*)(C16 + (size_t)r0 * HIDC + c) =
                __floats2half2_rn(acc[mt][nt][0], acc[mt][nt][1]);
            if (r1 < NN) *(__half2*)(C16 + (size_t)r1 * HIDC + c) =
                __floats2half2_rn(acc[mt][nt][2], acc[mt][nt][3]);
        }
    }
}

// ---------------- single-pass segment softmax + aggregation ------------------
// Static warp-per-node. Streaming data uses evict-first policy (ldcs/stcs) to
// protect g_lin16 L2 residency during the random row gather.
__global__ void k_edge(const float* __restrict__ bias,
                       int do_elu, int do_cvt, int jk_max) {
    const int n = (blockIdx.x * blockDim.x + threadIdx.x) >> 5;
    const int lane = threadIdx.x & 31;
    if (n >= NN) return;
    const int head = lane & 7;
    const int sub  = lane >> 3;
    const int beg = g_rowptr[n], end = g_rowptr[n + 1];
    const float edh = g_edst[n * 8 + head];
    const int c0 = head * 32 + sub * 8;

    float acc[8];
#pragma unroll
    for (int j = 0; j < 8; j++) acc[j] = 0.f;
    float sw = 0.f;

    int i = beg;
    for (; i + 2 <= end; i += 2) {
        const int s0 = __ldcs(&g_csrsrc[i]), s1 = __ldcs(&g_csrsrc[i + 1]);
        float t0 = g_esrc[s0 * 8 + head] + edh;
        float t1 = g_esrc[s1 * 8 + head] + edh;
        uint4 raw0 = *(const uint4*)(g_lin16 + (size_t)s0 * HIDC + c0);
        uint4 raw1 = *(const uint4*)(g_lin16 + (size_t)s1 * HIDC + c0);
        t0 = (t0 > 0.f) ? t0 : 0.2f * t0;
        t1 = (t1 > 0.f) ? t1 : 0.2f * t1;
        const float w0 = __expf(t0), w1 = __expf(t1);
        sw += w0 + w1;
        const __half2* h0 = (const __half2*)&raw0;
        const __half2* h1 = (const __half2*)&raw1;
#pragma unroll
        for (int q = 0; q < 4; q++) {
            float2 f0 = __half22float2(h0[q]);
            float2 f1 = __half22float2(h1[q]);
            acc[2*q]   = fmaf(w0, f0.x, fmaf(w1, f1.x, acc[2*q]));
            acc[2*q+1] = fmaf(w0, f0.y, fmaf(w1, f1.y, acc[2*q+1]));
        }
    }
    if (i < end) {
        const int s = __ldcs(&g_csrsrc[i]);
        float t = g_esrc[s * 8 + head] + edh;
        t = (t > 0.f) ? t : 0.2f * t;
        const float w = __expf(t);
        sw += w;
        uint4 raw = *(const uint4*)(g_lin16 + (size_t)s * HIDC + c0);
        const __half2* h2 = (const __half2*)&raw;
#pragma unroll
        for (int q = 0; q < 4; q++) {
            float2 f = __half22float2(h2[q]);
            acc[2*q]   = fmaf(w, f.x, acc[2*q]);
            acc[2*q+1] = fmaf(w, f.y, acc[2*q+1]);
        }
    }

    const float inv = 1.f / (sw + 1e-16f);
    float o[8];
#pragma unroll
    for (int j = 0; j < 8; j++) {
        float vv = acc[j] * inv + bias[c0 + j];
        if (do_elu) vv = (vv > 0.f) ? vv : (__expf(vv) - 1.f);
        o[j] = vv;
    }
    // running JK max in fp16 (evict-first: single-use per layer)
    __align__(16) __half hv[8];
#pragma unroll
    for (int j = 0; j < 8; j++) hv[j] = __float2half(o[j]);
    if (jk_max) {
        uint4 old = __ldcs((const uint4*)&g_jk[(size_t)n * HIDC + c0]);
        const __half* ov = (const __half*)&old;
#pragma unroll
        for (int j = 0; j < 8; j++) hv[j] = __hmax(hv[j], ov[j]);
    }
    __stcs((uint4*)&g_jk[(size_t)n * HIDC + c0], *(uint4*)hv);

    if (do_cvt) {
        __align__(16) __nv_bfloat16 hb[8];
#pragma unroll
        for (int j = 0; j < 8; j++) hb[j] = __float2bfloat16(o[j]);
        __stcs((uint4*)&g_abf[(size_t)n * 256 + c0], *(uint4*)hb);
    }
}

// ---------------- fused final linear (on fp16 JK buffer) + log_softmax ------
__global__ __launch_bounds__(160) void k_final(
    const float* __restrict__ Wf, const float* __restrict__ bf, float* __restrict__ out)
{
    __shared__ __align__(16) float sW[HIDC * OUTC];
    __shared__ float sb[OUTC];
    __shared__ __align__(16) float sl[32][OUTC];
    const int t = threadIdx.x;
    for (int i = t; i < HIDC * OUTC; i += 160) sW[i] = Wf[i];
    if (t < OUTC) sb[t] = bf[t];
    __syncthreads();

    const int r = t / 5;
    const int og = (t % 5) * 8;
    const int node = blockIdx.x * 32 + r;
    float acc[8];
#pragma unroll
    for (int j = 0; j < 8; j++) acc[j] = 0.f;
    const __half* pj = g_jk + (size_t)node * HIDC;
    for (int k = 0; k < HIDC; k += 2) {
        float2 vv = __half22float2(*(const __half2*)&pj[k]);
#pragma unroll
        for (int s = 0; s < 2; s++) {
            const float v = (s == 0) ? vv.x : vv.y;
            const float4* wp = (const float4*)&sW[(k + s) * OUTC + og];
            float4 w0 = wp[0], w1 = wp[1];
            acc[0] = fmaf(v, w0.x, acc[0]); acc[1] = fmaf(v, w0.y, acc[1]);
            acc[2] = fmaf(v, w0.z, acc[2]); acc[3] = fmaf(v, w0.w, acc[3]);
            acc[4] = fmaf(v, w1.x, acc[4]); acc[5] = fmaf(v, w1.y, acc[5]);
            acc[6] = fmaf(v, w1.z, acc[6]); acc[7] = fmaf(v, w1.w, acc[7]);
        }
    }
#pragma unroll
    for (int j = 0; j < 8; j++) acc[j] += sb[og + j];
    *(float4*)&sl[r][og]     = make_float4(acc[0], acc[1], acc[2], acc[3]);
    *(float4*)&sl[r][og + 4] = make_float4(acc[4], acc[5], acc[6], acc[7]);
    __syncthreads();

    if (t < 32) {
        const int nd = blockIdx.x * 32 + t;
        float m = -1e30f;
        for (int o = 0; o < OUTC; o++) m = fmaxf(m, sl[t][o]);
        float ssum = 0.f;
        for (int o = 0; o < OUTC; o++) ssum += expf(sl[t][o] - m);
        const float lse = m + logf(ssum);
        for (int o = 0; o < OUTC; o++) out[(size_t)nd * OUTC + o] = sl[t][o] - lse;
    }
}

// ---------------- launch ----------------
extern "C" void kernel_launch(void* const* d_in, const int* in_sizes, int n_in,
                              void* d_out, int out_size)
{
    (void)in_sizes; (void)n_in; (void)out_size;
    const float* x  = (const float*)d_in[0];
    const void*  ei = d_in[1];
    const float* W[3]  = {(const float*)d_in[2], (const float*)d_in[6],  (const float*)d_in[10]};
    const float* As[3] = {(const float*)d_in[3], (const float*)d_in[7],  (const float*)d_in[11]};
    const float* Ad[3] = {(const float*)d_in[4], (const float*)d_in[8],  (const float*)d_in[12]};
    const float* Bb[3] = {(const float*)d_in[5], (const float*)d_in[9],  (const float*)d_in[13]};
    const float* Wf = (const float*)d_in[14];
    const float* bf = (const float*)d_in[15];
    float* out = (float*)d_out;

    __half* lin16;
    __nv_bfloat16 *abf, *bbf;
    cudaGetSymbolAddress((void**)&lin16, g_lin16);
    cudaGetSymbolAddress((void**)&abf, g_abf);
    cudaGetSymbolAddress((void**)&bbf, g_bbf);

    // one-time host resources (no device memory): side stream + fork/join events
    static cudaStream_t s_csr = 0;
    static cudaEvent_t ev_fork = 0, ev_csr = 0;
    if (!s_csr) {
        cudaStreamCreateWithFlags(&s_csr, cudaStreamNonBlocking);
        cudaEventCreateWithFlags(&ev_fork, cudaEventDisableTiming);
        cudaEventCreateWithFlags(&ev_csr, cudaEventDisableTiming);
    }

    const int Ks[3]    = {500, 256, 256};
    const int Kpads[3] = {512, 256, 256};
    dim3 mgrid(2, NNP / 128);

    // ---- fork: CSR build on side stream (independent of dense chain) ----
    cudaEventRecord(ev_fork, 0);
    cudaStreamWaitEvent(s_csr, ev_fork, 0);
    k_zero<<<(NN + 255) / 256, 256, 0, s_csr>>>();
    k_detect<<<16, 256, 0, s_csr>>>((const int*)ei);
    k_hist<<<(ET + 255) / 256, 256, 0, s_csr>>>(ei);
    k_scan1<<<NSCB, SCB, 0, s_csr>>>();
    k_scan2<<<1, 256, 0, s_csr>>>();
    k_scan3<<<(NN + 255) / 256, 256, 0, s_csr>>>();
    k_scatter<<<(ET + 255) / 256, 256, 0, s_csr>>>(ei);
    cudaEventRecord(ev_csr, s_csr);

    // ---- dense chain on default stream ----
    k_cvtX<<<(NNP * 128 + 255) / 256, 256>>>(x);
    for (int l = 0; l < 3; l++)
        k_cvtW<<<(Kpads[l] * 256 + 255) / 256, 256>>>(W[l], bbf + (size_t)l * 256 * 512,
                                                       Ks[l], Kpads[l]);
    k_mma<<<mgrid, 256>>>(abf, bbf, As[0], Ad[0], lin16, Kpads[0]);

    // ---- join: edge needs the CSR ----
    cudaStreamWaitEvent(0, ev_csr, 0);
    k_edge<<<(NN * 32 + 255) / 256, 256>>>(Bb[0], 1, 1, 0);

    for (int l = 1; l < 3; l++) {
        k_mma<<<mgrid, 256>>>(abf, bbf + (size_t)l * 256 * 512,
                              As[l], Ad[l], lin16, Kpads[l]);
        k_edge<<<(NN * 32 + 255) / 256, 256>>>(Bb[l],
                                               (l < 2) ? 1 : 0, (l < 2) ? 1 : 0, 1);
    }
    k_final<<<NN / 32, 160>>>(Wf, bf, out);
}